// round 3
// baseline (speedup 1.0000x reference)
#include <cuda_runtime.h>
#include <math.h>

// Problem constants
#define T_TOT 8192   // B*N tokens
#define DD    1024
#define EE    8
#define RR    256

typedef unsigned long long u64;

// -------- scratch (__device__ globals; no allocations allowed) --------
__device__ int   g_count[EE];
__device__ int   g_sidx[EE * T_TOT];     // sidx = token*2 + k
__device__ float g_gate[EE * T_TOT];
__device__ float g_S[T_TOT * 2 * RR];    // 16 MB: gated silu(u)*v rows

// -------- f32x2 helpers (packed fp32 pipe, 2 FMA / instr) --------
__device__ __forceinline__ u64 fma2(u64 a, u64 b, u64 c) {
    u64 d;
    asm("fma.rn.f32x2 %0, %1, %2, %3;" : "=l"(d) : "l"(a), "l"(b), "l"(c));
    return d;
}
__device__ __forceinline__ u64 splat2(float v) {
    u64 d; unsigned r = __float_as_uint(v);
    asm("mov.b64 %0, {%1, %1};" : "=l"(d) : "r"(r));
    return d;
}
__device__ __forceinline__ float2 unpack2(u64 a) {
    unsigned lo, hi;
    asm("mov.b64 {%0, %1}, %2;" : "=r"(lo), "=r"(hi) : "l"(a));
    return make_float2(__uint_as_float(lo), __uint_as_float(hi));
}

// -------- init: zero output + counters --------
__global__ void init_kernel(float4* out4, int n4) {
    if (blockIdx.x == 0 && threadIdx.x < EE) g_count[threadIdx.x] = 0;
    int stride = gridDim.x * blockDim.x;
    for (int i = blockIdx.x * blockDim.x + threadIdx.x; i < n4; i += stride)
        out4[i] = make_float4(0.f, 0.f, 0.f, 0.f);
}

// -------- router: one warp per token --------
__global__ void router_kernel(const float* __restrict__ x,
                              const float* __restrict__ gw) {
    int warp = (blockIdx.x * blockDim.x + threadIdx.x) >> 5;
    int lane = threadIdx.x & 31;
    if (warp >= T_TOT) return;
    const float* xr = x + (size_t)warp * DD;

    float acc[EE];
#pragma unroll
    for (int e = 0; e < EE; e++) acc[e] = 0.f;

    for (int d = lane * 4; d < DD; d += 32 * 4) {
        float4 xv = *(const float4*)(xr + d);
        const float* xp = (const float*)&xv;
#pragma unroll
        for (int j = 0; j < 4; j++) {
            float xs = xp[j];
            float4 g0 = *(const float4*)(gw + (size_t)(d + j) * EE);
            float4 g1 = *(const float4*)(gw + (size_t)(d + j) * EE + 4);
            acc[0] += xs * g0.x; acc[1] += xs * g0.y;
            acc[2] += xs * g0.z; acc[3] += xs * g0.w;
            acc[4] += xs * g1.x; acc[5] += xs * g1.y;
            acc[6] += xs * g1.z; acc[7] += xs * g1.w;
        }
    }
#pragma unroll
    for (int e = 0; e < EE; e++)
#pragma unroll
        for (int off = 16; off; off >>= 1)
            acc[e] += __shfl_xor_sync(0xFFFFFFFFu, acc[e], off);

    if (lane == 0) {
        int i0 = 0; float v0 = acc[0];
#pragma unroll
        for (int e = 1; e < EE; e++) if (acc[e] > v0) { v0 = acc[e]; i0 = e; }
        int i1 = -1; float v1 = -INFINITY;
#pragma unroll
        for (int e = 0; e < EE; e++) if (e != i0 && acc[e] > v1) { v1 = acc[e]; i1 = e; }
        float w0 = 1.f / (1.f + expf(v1 - v0));   // softmax over (v0,v1), v0 = max
        float w1 = 1.f - w0;
        int p0 = atomicAdd(&g_count[i0], 1);
        g_sidx[i0 * T_TOT + p0] = warp * 2 + 0;
        g_gate[i0 * T_TOT + p0] = w0;
        int p1 = atomicAdd(&g_count[i1], 1);
        g_sidx[i1 * T_TOT + p1] = warp * 2 + 1;
        g_gate[i1 * T_TOT + p1] = w1;
    }
}

// -------- pass1: S = gate * silu(x Wu_e) * (x Wv_e), tiles of 32 rows x 256 (=R) --------
#define TM1 32
#define TK1 16
__global__ __launch_bounds__(256, 2)
void pass1_kernel(const float* __restrict__ x,
                  const float* __restrict__ Wu,
                  const float* __restrict__ Wv) {
    int e = blockIdx.y;
    int cnt = g_count[e];
    int mbase = blockIdx.x * TM1;
    if (mbase >= cnt) return;

    __shared__ __align__(16) float xs[TK1][TM1];     // [k][m]
    __shared__ __align__(16) float wus[TK1][RR];
    __shared__ __align__(16) float wvs[TK1][RR];
    __shared__ int   s_tok[TM1];
    __shared__ int   s_sidx[TM1];
    __shared__ float s_gate[TM1];

    int tid = threadIdx.x;
    if (tid < TM1) {
        int slot = mbase + tid;
        bool valid = slot < cnt;
        int sidx = valid ? g_sidx[e * T_TOT + slot] : -1;
        s_sidx[tid] = sidx;
        s_tok[tid]  = valid ? (sidx >> 1) : 0;
        s_gate[tid] = valid ? g_gate[e * T_TOT + slot] : 0.f;
    }
    __syncthreads();

    int nx  = tid & 63;       // 64 groups over R: n0 = nx*4
    int my  = tid >> 6;       // 4 groups over M: m0l = my*8
    int n0  = nx * 4;
    int m0l = my * 8;

    u64 accU[4][4], accV[4][4];
#pragma unroll
    for (int i = 0; i < 4; i++)
#pragma unroll
        for (int j = 0; j < 4; j++) { accU[i][j] = 0ull; accV[i][j] = 0ull; }

    const float* WuE = Wu + (size_t)e * DD * RR;
    const float* WvE = Wv + (size_t)e * DD * RR;

    for (int d0 = 0; d0 < DD; d0 += TK1) {
        // gather x tile (transposed) : 32 rows x 16 k
        if (tid < 128) {
            int m = tid >> 2, kb = (tid & 3) * 4;
            float4 xv = *(const float4*)(x + (size_t)s_tok[m] * DD + d0 + kb);
            xs[kb + 0][m] = xv.x; xs[kb + 1][m] = xv.y;
            xs[kb + 2][m] = xv.z; xs[kb + 3][m] = xv.w;
        }
        // gather weight tiles : 16 x 256 each
#pragma unroll
        for (int i = 0; i < 4; i++) {
            int slot = tid + i * 256;
            int k = slot >> 6, c = (slot & 63) << 2;
            *(float4*)&wus[k][c] = *(const float4*)(WuE + (size_t)(d0 + k) * RR + c);
            *(float4*)&wvs[k][c] = *(const float4*)(WvE + (size_t)(d0 + k) * RR + c);
        }
        __syncthreads();
#pragma unroll
        for (int kk = 0; kk < TK1; kk++) {
            ulonglong2 xa = *(const ulonglong2*)&xs[kk][m0l];
            ulonglong2 xb = *(const ulonglong2*)&xs[kk][m0l + 4];
            u64 xm[4] = { xa.x, xa.y, xb.x, xb.y };
            float4 wu4 = *(const float4*)&wus[kk][n0];
            float4 wv4 = *(const float4*)&wvs[kk][n0];
            u64 wu[4] = { splat2(wu4.x), splat2(wu4.y), splat2(wu4.z), splat2(wu4.w) };
            u64 wv[4] = { splat2(wv4.x), splat2(wv4.y), splat2(wv4.z), splat2(wv4.w) };
#pragma unroll
            for (int m2 = 0; m2 < 4; m2++)
#pragma unroll
                for (int n = 0; n < 4; n++) {
                    accU[m2][n] = fma2(xm[m2], wu[n], accU[m2][n]);
                    accV[m2][n] = fma2(xm[m2], wv[n], accV[m2][n]);
                }
        }
        __syncthreads();
    }

    // epilogue: s = gate * silu(u) * v  -> g_S[sidx]
#pragma unroll
    for (int m2 = 0; m2 < 4; m2++) {
#pragma unroll
        for (int h = 0; h < 2; h++) {
            int mrow = m0l + 2 * m2 + h;
            int slot = mbase + mrow;
            if (slot >= cnt) continue;
            int sidx = s_sidx[mrow];
            float g = s_gate[mrow];
            float4 sv;
            float* svp = (float*)&sv;
#pragma unroll
            for (int n = 0; n < 4; n++) {
                float2 u2 = unpack2(accU[m2][n]);
                float2 v2 = unpack2(accV[m2][n]);
                float u = h ? u2.y : u2.x;
                float v = h ? v2.y : v2.x;
                float sig = 1.f / (1.f + __expf(-u));
                svp[n] = g * (u * sig) * v;
            }
            *(float4*)(g_S + (size_t)sidx * RR + n0) = sv;
        }
    }
}

// -------- pass2: out[token] += S_row * Wo_e, tiles 64 rows x 128 cols, K=256 --------
#define TM2 64
#define TN2 128
#define TK2 32
__global__ __launch_bounds__(256, 2)
void pass2_kernel(const float* __restrict__ Wo, float* __restrict__ out) {
    int e = blockIdx.z;
    int cnt = g_count[e];
    int mbase = blockIdx.x * TM2;
    if (mbase >= cnt) return;
    int n0g = blockIdx.y * TN2;

    __shared__ __align__(16) float ss[TK2][TM2];    // 8 KB  [k][m]
    __shared__ __align__(16) float wos[TK2][TN2];   // 16 KB [k][n]
    __shared__ int s_tok[TM2];
    __shared__ int s_sidx[TM2];

    int tid = threadIdx.x;
    if (tid < TM2) {
        int slot = mbase + tid;
        bool valid = slot < cnt;
        int sidx = valid ? g_sidx[e * T_TOT + slot] : 0;  // 0 is a safe, valid row
        s_sidx[tid] = sidx;
        s_tok[tid]  = sidx >> 1;
    }
    __syncthreads();

    int nx  = tid & 31;       // n0 = nx*4 over 128
    int my  = tid >> 5;       // m0l = my*8 over 64
    int n0  = nx * 4;
    int m0l = my * 8;

    u64 acc[4][4];
#pragma unroll
    for (int i = 0; i < 4; i++)
#pragma unroll
        for (int j = 0; j < 4; j++) acc[i][j] = 0ull;

    const float* WoE = Wo + (size_t)e * RR * DD;

    for (int k0 = 0; k0 < RR; k0 += TK2) {
        // gather S tile (transposed): 64 rows x 32 k
#pragma unroll
        for (int i = 0; i < 2; i++) {
            int slot = tid + i * 256;
            int m = slot >> 3, kb = (slot & 7) << 2;
            float4 sv = *(const float4*)(g_S + (size_t)s_sidx[m] * RR + k0 + kb);
            ss[kb + 0][m] = sv.x; ss[kb + 1][m] = sv.y;
            ss[kb + 2][m] = sv.z; ss[kb + 3][m] = sv.w;
        }
        // gather Wo tile: 32 x 128
#pragma unroll
        for (int i = 0; i < 4; i++) {
            int slot = tid + i * 256;
            int k = slot >> 5, c = (slot & 31) << 2;
            *(float4*)&wos[k][c] =
                *(const float4*)(WoE + (size_t)(k0 + k) * DD + n0g + c);
        }
        __syncthreads();
#pragma unroll
        for (int kk = 0; kk < TK2; kk++) {
            ulonglong2 xa = *(const ulonglong2*)&ss[kk][m0l];
            ulonglong2 xb = *(const ulonglong2*)&ss[kk][m0l + 4];
            u64 xm[4] = { xa.x, xa.y, xb.x, xb.y };
            float4 w4 = *(const float4*)&wos[kk][n0];
            u64 w[4] = { splat2(w4.x), splat2(w4.y), splat2(w4.z), splat2(w4.w) };
#pragma unroll
            for (int m2 = 0; m2 < 4; m2++)
#pragma unroll
                for (int n = 0; n < 4; n++)
                    acc[m2][n] = fma2(xm[m2], w[n], acc[m2][n]);
        }
        __syncthreads();
    }

    // epilogue: atomic accumulate into out (each token has exactly 2 experts)
#pragma unroll
    for (int m2 = 0; m2 < 4; m2++) {
#pragma unroll
        for (int h = 0; h < 2; h++) {
            int mrow = m0l + 2 * m2 + h;
            int slot = mbase + mrow;
            if (slot >= cnt) continue;
            int t = s_tok[mrow];
            float* orow = out + (size_t)t * DD + n0g + n0;
#pragma unroll
            for (int n = 0; n < 4; n++) {
                float2 a2 = unpack2(acc[m2][n]);
                atomicAdd(orow + n, h ? a2.y : a2.x);
            }
        }
    }
}

// -------- launch --------
extern "C" void kernel_launch(void* const* d_in, const int* in_sizes, int n_in,
                              void* d_out, int out_size) {
    (void)in_sizes; (void)n_in;
    const float* x  = (const float*)d_in[0];
    const float* gw = (const float*)d_in[1];
    const float* Wu = (const float*)d_in[2];
    const float* Wv = (const float*)d_in[3];
    const float* Wo = (const float*)d_in[4];
    float* out = (float*)d_out;

    int n4 = out_size / 4;
    init_kernel<<<1024, 256>>>((float4*)out, n4);
    router_kernel<<<T_TOT / 8, 256>>>(x, gw);

    dim3 g1(T_TOT / TM1, EE);                 // 256 x 8 tiles (early-exit on count)
    pass1_kernel<<<g1, 256>>>(x, Wu, Wv);

    dim3 g2(T_TOT / TM2, DD / TN2, EE);       // 128 x 8 x 8 tiles
    pass2_kernel<<<g2, 256>>>(Wo, out);
}